// round 15
// baseline (speedup 1.0000x reference)
#include <cuda_runtime.h>
#include <cuda_fp16.h>
#include <cstdint>

#define N_NODES 200000
#define N_GRAPHS 4000
#define C1 32
#define H 64
#define CAP 96   // per-node bucket capacity (deg ~ Poisson(16); P(>96) ~ 0)

// ---------------- scratch (device globals; allocation forbidden) ------------
__device__ __align__(16) float g_agg1[(size_t)N_NODES * C1];   // layer1 neighbor MEAN (fp32)
__device__ __align__(16) float g_h1[(size_t)N_NODES * H];       // layer1 output (fp32, self term)
__device__ __align__(16) __half g_h1h[(size_t)N_NODES * H];     // layer1 output (fp16, gather2)
__device__ __align__(16) __half g_xh[(size_t)N_NODES * C1];     // x in fp16 (gather1)
__device__ __align__(16) float g_agg2[(size_t)N_NODES * H];     // layer2 neighbor MEAN (fp32)
__device__ __align__(16) float g_pool[(size_t)N_GRAPHS * H];    // pooled sums
__device__ __align__(16) float g_cnt[N_GRAPHS];                 // nodes per graph
__device__ int g_cursor[N_NODES];                 // per-node fill cursor == degree
__device__ int g_csr[(size_t)N_NODES * CAP];      // bucketed src ids
__device__ int g_idx_is_32;

__device__ __forceinline__ int load_idx(const void* base, long long i) {
    if (g_idx_is_32) return ((const int*)base)[i];
    return (int)((const long long*)base)[i];
}

// ---------------- packed f32x2 helpers (PTX-only FFMA2) ---------------------
__device__ __forceinline__ unsigned long long pack2(float a, float b) {
    unsigned long long r;
    asm("mov.b64 %0, {%1, %2};" : "=l"(r)
        : "r"(__float_as_uint(a)), "r"(__float_as_uint(b)));
    return r;
}
__device__ __forceinline__ unsigned long long bcast2(float v) {
    unsigned long long r;
    asm("mov.b64 %0, {%1, %1};" : "=l"(r) : "r"(__float_as_uint(v)));
    return r;
}
__device__ __forceinline__ void ffma2(unsigned long long& d,
                                      unsigned long long a,
                                      unsigned long long b) {
    asm("fma.rn.f32x2 %0, %1, %2, %0;" : "+l"(d) : "l"(a), "l"(b));
}
__device__ __forceinline__ void unpack2(unsigned long long v, float& lo, float& hi) {
    unsigned a, b;
    asm("mov.b64 {%0, %1}, %2;" : "=r"(a), "=r"(b) : "l"(v));
    lo = __uint_as_float(a);
    hi = __uint_as_float(b);
}

// 8-byte raw half4 accumulate into float4
__device__ __forceinline__ void add_half4(float4& acc, uint2 raw) {
    __half2 h0 = *reinterpret_cast<__half2*>(&raw.x);
    __half2 h1 = *reinterpret_cast<__half2*>(&raw.y);
    float2 f0 = __half22float2(h0);
    float2 f1 = __half22float2(h1);
    acc.x += f0.x; acc.y += f0.y; acc.z += f1.x; acc.w += f1.y;
}

// ---------------- zero + index-dtype probe + x->fp16 ------------------------
__global__ void k_zero(const float* __restrict__ x, const void* ei, int n_elem) {
    int i = blockIdx.x * blockDim.x + threadIdx.x;
    int stride = gridDim.x * blockDim.x;
    if (blockIdx.x == 0 && threadIdx.x == 0) {
        const long long* p = (const long long*)ei;
        int cnt = n_elem < 64 ? n_elem : 64;
        int is32 = 0;
        for (int k = 0; k < cnt; k++) {
            long long v = p[k];
            if (v < 0 || v >= N_NODES) { is32 = 1; break; }
        }
        g_idx_is_32 = is32;
    }
    for (int j = i; j < N_GRAPHS * H; j += stride) g_pool[j] = 0.f;
    for (int j = i; j < N_GRAPHS; j += stride) g_cnt[j] = 0.f;
    for (int j = i; j < N_NODES; j += stride) g_cursor[j] = 0;
    // convert x to fp16 (float2 -> half2 per iteration)
    const float2* x2 = reinterpret_cast<const float2*>(x);
    __half2* xh2 = reinterpret_cast<__half2*>(g_xh);
    for (int j = i; j < N_NODES * C1 / 2; j += stride)
        xh2[j] = __float22half2_rn(x2[j]);
}

// ---------------- bucketed scatter ------------------------------------------
__global__ void k_scatter(const void* __restrict__ ei, int E) {
    int e = blockIdx.x * blockDim.x + threadIdx.x;
    if (e >= E) return;
    int sidx, d;
    if (g_idx_is_32) {
        const int* p = (const int*)ei;
        sidx = p[e];
        d = p[(long long)e + E];
    } else {
        const long long* p = (const long long*)ei;
        sidx = (int)p[e];
        d = (int)p[(long long)e + E];
    }
    int pos = atomicAdd(&g_cursor[d], 1);
    if (pos < CAP) g_csr[(size_t)d * CAP + pos] = sidx;
}

// ---------------- layer-1 gather from fp16 x (64 B/edge) --------------------
// lane = sub*8 + g : sub in [0,4), g in [0,8) -> 4 halves (8 B) per lane
__global__ void __launch_bounds__(256) k_gather1() {
    int warp = threadIdx.x >> 5, lane = threadIdx.x & 31;
    int n = blockIdx.x * 8 + warp;
    if (n >= N_NODES) return;
    int deg = g_cursor[n];
    int cnt = deg < CAP ? deg : CAP;
    int off = n * CAP;
    int end = off + cnt;
    int sub = lane >> 3, g = lane & 7;

    float4 acc = make_float4(0.f, 0.f, 0.f, 0.f);
    int e = off + sub;
    while (e < end) {
        int s[8];
#pragma unroll
        for (int i = 0; i < 8; i++) {
            int ee = e + 4 * i;
            s[i] = (ee < end) ? g_csr[ee] : 0;
        }
#pragma unroll
        for (int i = 0; i < 8; i++) {
            if (e + 4 * i < end) {
                uint2 raw = *reinterpret_cast<const uint2*>(g_xh + (size_t)s[i] * C1 + g * 4);
                add_half4(acc, raw);
            }
        }
        e += 32;
    }
#pragma unroll
    for (int d = 16; d >= 8; d >>= 1) {
        acc.x += __shfl_xor_sync(0xffffffff, acc.x, d);
        acc.y += __shfl_xor_sync(0xffffffff, acc.y, d);
        acc.z += __shfl_xor_sync(0xffffffff, acc.z, d);
        acc.w += __shfl_xor_sync(0xffffffff, acc.w, d);
    }
    if (lane < 8) {
        float inv = 1.f / fmaxf((float)deg, 1.f);
        acc.x *= inv; acc.y *= inv; acc.z *= inv; acc.w *= inv;
        *reinterpret_cast<float4*>(g_agg1 + (size_t)n * C1 + g * 4) = acc;
    }
}

// ---------------- layer-1 node update: f32x2, 4 nodes/thread, half-H passes -
// also writes fp16 copy of h1 for gather2
__global__ void __launch_bounds__(128, 1) k_node1(const float* __restrict__ x,
                                                  const float* __restrict__ Wl,
                                                  const float* __restrict__ b,
                                                  const float* __restrict__ Wr) {
    __shared__ __align__(16) float sWlT[C1 * H];   // [k][j]
    __shared__ __align__(16) float sWrT[C1 * H];
    __shared__ float sb[H];
    for (int i = threadIdx.x; i < H * C1; i += blockDim.x) {
        int j = i / C1, k = i % C1;
        sWlT[k * H + j] = Wl[i];
        sWrT[k * H + j] = Wr[i];
    }
    for (int i = threadIdx.x; i < H; i += blockDim.x) sb[i] = b[i];
    __syncthreads();

    int n0 = (blockIdx.x * blockDim.x + threadIdx.x) * 4;
    if (n0 >= N_NODES) return;   // N_NODES % 4 == 0

#pragma unroll 1
    for (int jh = 0; jh < 2; jh++) {
        int jb = jh * (H / 2);
        unsigned long long acc[4][H / 4];
#pragma unroll
        for (int p = 0; p < H / 4; p++) {
            unsigned long long bb = pack2(sb[jb + 2 * p], sb[jb + 2 * p + 1]);
#pragma unroll
            for (int i = 0; i < 4; i++) acc[i][p] = bb;
        }

#pragma unroll 1
        for (int kc = 0; kc < C1 / 4; kc++) {
            float am[4][4], xm[4][4];
#pragma unroll
            for (int i = 0; i < 4; i++) {
                float4 a = *reinterpret_cast<const float4*>(g_agg1 + (size_t)(n0 + i) * C1 + kc * 4);
                float4 xb = *reinterpret_cast<const float4*>(x + (size_t)(n0 + i) * C1 + kc * 4);
                am[i][0] = a.x; am[i][1] = a.y; am[i][2] = a.z; am[i][3] = a.w;
                xm[i][0] = xb.x; xm[i][1] = xb.y; xm[i][2] = xb.z; xm[i][3] = xb.w;
            }
#pragma unroll
            for (int t = 0; t < 4; t++) {
                int k = kc * 4 + t;
                unsigned long long bm[4], bx[4];
#pragma unroll
                for (int i = 0; i < 4; i++) {
                    bm[i] = bcast2(am[i][t]);
                    bx[i] = bcast2(xm[i][t]);
                }
#pragma unroll
                for (int jq = 0; jq < H / 8; jq++) {
                    ulonglong2 wl = *reinterpret_cast<const ulonglong2*>(&sWlT[k * H + jb + jq * 4]);
                    ulonglong2 wr = *reinterpret_cast<const ulonglong2*>(&sWrT[k * H + jb + jq * 4]);
#pragma unroll
                    for (int i = 0; i < 4; i++) {
                        ffma2(acc[i][jq * 2 + 0], bm[i], wl.x);
                        ffma2(acc[i][jq * 2 + 1], bm[i], wl.y);
                        ffma2(acc[i][jq * 2 + 0], bx[i], wr.x);
                        ffma2(acc[i][jq * 2 + 1], bx[i], wr.y);
                    }
                }
            }
        }
#pragma unroll
        for (int i = 0; i < 4; i++) {
#pragma unroll
            for (int jq = 0; jq < H / 8; jq++) {
                float f0, f1, f2, f3;
                unpack2(acc[i][jq * 2 + 0], f0, f1);
                unpack2(acc[i][jq * 2 + 1], f2, f3);
                float4 o;
                o.x = fmaxf(f0, 0.f); o.y = fmaxf(f1, 0.f);
                o.z = fmaxf(f2, 0.f); o.w = fmaxf(f3, 0.f);
                *reinterpret_cast<float4*>(&g_h1[(size_t)(n0 + i) * H + jb + jq * 4]) = o;
                // fp16 copy for gather2
                __half2 h01 = __floats2half2_rn(o.x, o.y);
                __half2 h23 = __floats2half2_rn(o.z, o.w);
                uint2 hraw;
                hraw.x = *reinterpret_cast<unsigned*>(&h01);
                hraw.y = *reinterpret_cast<unsigned*>(&h23);
                *reinterpret_cast<uint2*>(g_h1h + (size_t)(n0 + i) * H + jb + jq * 4) = hraw;
            }
        }
    }
}

// ---------------- layer-2 gather from fp16 h1 (128 B/edge) ------------------
// lane = sub*16 + g : sub in [0,2), g in [0,16) -> 4 halves (8 B) per lane
__global__ void __launch_bounds__(256) k_gather2() {
    int warp = threadIdx.x >> 5, lane = threadIdx.x & 31;
    int n = blockIdx.x * 8 + warp;
    if (n >= N_NODES) return;
    int deg = g_cursor[n];
    int cnt = deg < CAP ? deg : CAP;
    int off = n * CAP;
    int end = off + cnt;
    int sub = lane >> 4, g = lane & 15;

    float4 acc = make_float4(0.f, 0.f, 0.f, 0.f);
    int e = off + sub;
    while (e < end) {
        int s[8];
#pragma unroll
        for (int i = 0; i < 8; i++) {
            int ee = e + 2 * i;
            s[i] = (ee < end) ? g_csr[ee] : 0;
        }
#pragma unroll
        for (int i = 0; i < 8; i++) {
            if (e + 2 * i < end) {
                uint2 raw = *reinterpret_cast<const uint2*>(g_h1h + (size_t)s[i] * H + g * 4);
                add_half4(acc, raw);
            }
        }
        e += 16;
    }
    acc.x += __shfl_xor_sync(0xffffffff, acc.x, 16);
    acc.y += __shfl_xor_sync(0xffffffff, acc.y, 16);
    acc.z += __shfl_xor_sync(0xffffffff, acc.z, 16);
    acc.w += __shfl_xor_sync(0xffffffff, acc.w, 16);
    if (lane < 16) {
        float inv = 1.f / fmaxf((float)deg, 1.f);
        acc.x *= inv; acc.y *= inv; acc.z *= inv; acc.w *= inv;
        *reinterpret_cast<float4*>(g_agg2 + (size_t)n * H + g * 4) = acc;
    }
}

// ---------------- layer-2 node update + pooling: f32x2, 2 nodes/thread ------
__global__ void __launch_bounds__(128, 1) k_node2(const void* __restrict__ batch,
                                                  const float* __restrict__ Wl,
                                                  const float* __restrict__ b,
                                                  const float* __restrict__ Wr) {
    __shared__ __align__(16) float sWlT[H * H];   // [k][j]
    __shared__ __align__(16) float sWrT[H * H];
    __shared__ float sb[H];
    for (int i = threadIdx.x; i < H * H; i += blockDim.x) {
        int j = i / H, k = i % H;
        sWlT[k * H + j] = Wl[i];
        sWrT[k * H + j] = Wr[i];
    }
    for (int i = threadIdx.x; i < H; i += blockDim.x) sb[i] = b[i];
    __syncthreads();

    int n0 = (blockIdx.x * blockDim.x + threadIdx.x) * 2;
    if (n0 >= N_NODES) return;
    int n1 = n0 + 1;

    unsigned long long acc0[H / 2], acc1[H / 2];
#pragma unroll
    for (int p = 0; p < H / 2; p++) {
        unsigned long long bb = pack2(sb[2 * p], sb[2 * p + 1]);
        acc0[p] = bb;
        acc1[p] = bb;
    }

    const float4* ag0 = reinterpret_cast<const float4*>(g_agg2 + (size_t)n0 * H);
    const float4* hr0 = reinterpret_cast<const float4*>(g_h1 + (size_t)n0 * H);
    const float4* ag1 = reinterpret_cast<const float4*>(g_agg2 + (size_t)n1 * H);
    const float4* hr1 = reinterpret_cast<const float4*>(g_h1 + (size_t)n1 * H);

#pragma unroll 1
    for (int kc = 0; kc < H / 4; kc++) {
        float4 a0 = ag0[kc], h0 = hr0[kc];
        float4 a1 = ag1[kc], h1 = hr1[kc];
        float am0[4] = {a0.x, a0.y, a0.z, a0.w};
        float hm0[4] = {h0.x, h0.y, h0.z, h0.w};
        float am1[4] = {a1.x, a1.y, a1.z, a1.w};
        float hm1[4] = {h1.x, h1.y, h1.z, h1.w};
#pragma unroll
        for (int t = 0; t < 4; t++) {
            int k = kc * 4 + t;
            unsigned long long bm0 = bcast2(am0[t]);
            unsigned long long bh0 = bcast2(hm0[t]);
            unsigned long long bm1 = bcast2(am1[t]);
            unsigned long long bh1 = bcast2(hm1[t]);
#pragma unroll
            for (int jq = 0; jq < H / 4; jq++) {
                ulonglong2 wl = *reinterpret_cast<const ulonglong2*>(&sWlT[k * H + jq * 4]);
                ulonglong2 wr = *reinterpret_cast<const ulonglong2*>(&sWrT[k * H + jq * 4]);
                ffma2(acc0[jq * 2 + 0], bm0, wl.x);
                ffma2(acc0[jq * 2 + 1], bm0, wl.y);
                ffma2(acc0[jq * 2 + 0], bh0, wr.x);
                ffma2(acc0[jq * 2 + 1], bh0, wr.y);
                ffma2(acc1[jq * 2 + 0], bm1, wl.x);
                ffma2(acc1[jq * 2 + 1], bm1, wl.y);
                ffma2(acc1[jq * 2 + 0], bh1, wr.x);
                ffma2(acc1[jq * 2 + 1], bh1, wr.y);
            }
        }
    }

    int bg0 = load_idx(batch, n0);
    int bg1 = load_idx(batch, n1);
    float* pr0 = g_pool + (size_t)bg0 * H;
    float* pr1 = g_pool + (size_t)bg1 * H;
#pragma unroll
    for (int jq = 0; jq < H / 4; jq++) {
        float f0, f1, f2, f3;
        unpack2(acc0[jq * 2 + 0], f0, f1);
        unpack2(acc0[jq * 2 + 1], f2, f3);
        float4 o;
        o.x = fmaxf(f0, 0.f); o.y = fmaxf(f1, 0.f);
        o.z = fmaxf(f2, 0.f); o.w = fmaxf(f3, 0.f);
        atomicAdd(reinterpret_cast<float4*>(pr0 + jq * 4), o);
        unpack2(acc1[jq * 2 + 0], f0, f1);
        unpack2(acc1[jq * 2 + 1], f2, f3);
        o.x = fmaxf(f0, 0.f); o.y = fmaxf(f1, 0.f);
        o.z = fmaxf(f2, 0.f); o.w = fmaxf(f3, 0.f);
        atomicAdd(reinterpret_cast<float4*>(pr1 + jq * 4), o);
    }
    atomicAdd(&g_cnt[bg0], 1.0f);
    atomicAdd(&g_cnt[bg1], 1.0f);
}

// ---------------- final linear ----------------------------------------------
__global__ void k_final(const float* __restrict__ Wlin,
                        const float* __restrict__ blin,
                        float* __restrict__ out) {
    int g = blockIdx.x * blockDim.x + threadIdx.x;
    if (g >= N_GRAPHS) return;
    float invc = 1.0f / fmaxf(g_cnt[g], 1.0f);
    float a0 = blin[0], a1 = blin[1];
#pragma unroll
    for (int j = 0; j < H; j++) {
        float p = g_pool[(size_t)g * H + j] * invc;
        a0 += p * Wlin[j];
        a1 += p * Wlin[H + j];
    }
    out[g * 2 + 0] = a0;
    out[g * 2 + 1] = a1;
}

// ---------------------------------------------------------------------------
extern "C" void kernel_launch(void* const* d_in, const int* in_sizes, int n_in,
                              void* d_out, int out_size) {
    const float* x     = (const float*)d_in[0];
    const void*  ei    = d_in[1];
    const void*  batch = d_in[2];
    const float* W1_l  = (const float*)d_in[3];
    const float* b1    = (const float*)d_in[4];
    const float* W1_r  = (const float*)d_in[5];
    const float* W2_l  = (const float*)d_in[6];
    const float* b2    = (const float*)d_in[7];
    const float* W2_r  = (const float*)d_in[8];
    const float* W_lin = (const float*)d_in[9];
    const float* b_lin = (const float*)d_in[10];
    float* out = (float*)d_out;

    int E = in_sizes[1] / 2;
    int eb = (E + 255) / 256;
    int nb8 = (N_NODES + 7) / 8;
    int np4 = (N_NODES / 4 + 127) / 128;
    int np2 = (N_NODES / 2 + 127) / 128;

    k_zero<<<512, 256>>>(x, ei, in_sizes[1]);
    k_scatter<<<eb, 256>>>(ei, E);
    k_gather1<<<nb8, 256>>>();
    k_node1<<<np4, 128>>>(x, W1_l, b1, W1_r);
    k_gather2<<<nb8, 256>>>();
    k_node2<<<np2, 128>>>(batch, W2_l, b2, W2_r);
    k_final<<<(N_GRAPHS + 127) / 128, 128>>>(W_lin, b_lin, out);
}

// round 16
// speedup vs baseline: 1.0350x; 1.0350x over previous
#include <cuda_runtime.h>
#include <cstdint>

#define N_NODES 200000
#define N_GRAPHS 4000
#define C1 32
#define H 64
#define CAP 96   // per-node bucket capacity (deg ~ Poisson(16); P(>96) ~ 0)

// ---------------- scratch (device globals; allocation forbidden) ------------
__device__ __align__(16) float g_agg1[(size_t)N_NODES * C1];   // layer1 neighbor MEAN
__device__ __align__(16) float g_h1[(size_t)N_NODES * H];       // layer1 output
__device__ __align__(16) float g_agg2[(size_t)N_NODES * H];     // layer2 neighbor MEAN
__device__ __align__(16) float g_pool[(size_t)N_GRAPHS * H];    // pooled sums
__device__ __align__(16) float g_cnt[N_GRAPHS];                 // nodes per graph
__device__ int g_cursor[N_NODES];                 // per-node fill cursor == degree
__device__ int g_csr[(size_t)N_NODES * CAP];      // bucketed src ids
__device__ int g_idx_is_32;

__device__ __forceinline__ int load_idx(const void* base, long long i) {
    if (g_idx_is_32) return ((const int*)base)[i];
    return (int)((const long long*)base)[i];
}

// ---------------- packed f32x2 helpers (PTX-only FFMA2) ---------------------
__device__ __forceinline__ unsigned long long pack2(float a, float b) {
    unsigned long long r;
    asm("mov.b64 %0, {%1, %2};" : "=l"(r)
        : "r"(__float_as_uint(a)), "r"(__float_as_uint(b)));
    return r;
}
__device__ __forceinline__ unsigned long long bcast2(float v) {
    unsigned long long r;
    asm("mov.b64 %0, {%1, %1};" : "=l"(r) : "r"(__float_as_uint(v)));
    return r;
}
__device__ __forceinline__ void ffma2(unsigned long long& d,
                                      unsigned long long a,
                                      unsigned long long b) {
    asm("fma.rn.f32x2 %0, %1, %2, %0;" : "+l"(d) : "l"(a), "l"(b));
}
__device__ __forceinline__ void unpack2(unsigned long long v, float& lo, float& hi) {
    unsigned a, b;
    asm("mov.b64 {%0, %1}, %2;" : "=r"(a), "=r"(b) : "l"(v));
    lo = __uint_as_float(a);
    hi = __uint_as_float(b);
}

// ---------------- zero + index-dtype probe ----------------------------------
__global__ void k_zero(const void* ei, int n_elem) {
    int i = blockIdx.x * blockDim.x + threadIdx.x;
    int stride = gridDim.x * blockDim.x;
    if (blockIdx.x == 0 && threadIdx.x == 0) {
        const long long* p = (const long long*)ei;
        int cnt = n_elem < 64 ? n_elem : 64;
        int is32 = 0;
        for (int k = 0; k < cnt; k++) {
            long long v = p[k];
            if (v < 0 || v >= N_NODES) { is32 = 1; break; }
        }
        g_idx_is_32 = is32;
    }
    for (int j = i; j < N_GRAPHS * H; j += stride) g_pool[j] = 0.f;
    for (int j = i; j < N_GRAPHS; j += stride) g_cnt[j] = 0.f;
    for (int j = i; j < N_NODES; j += stride) g_cursor[j] = 0;
}

// ---------------- bucketed scatter ------------------------------------------
__global__ void k_scatter(const void* __restrict__ ei, int E) {
    int e = blockIdx.x * blockDim.x + threadIdx.x;
    if (e >= E) return;
    int sidx, d;
    if (g_idx_is_32) {
        const int* p = (const int*)ei;
        sidx = __ldg(&p[e]);
        d = __ldg(&p[(long long)e + E]);
    } else {
        const long long* p = (const long long*)ei;
        sidx = (int)__ldg(&p[e]);
        d = (int)__ldg(&p[(long long)e + E]);
    }
    int pos = atomicAdd(&g_cursor[d], 1);
    if (pos < CAP) g_csr[(size_t)d * CAP + pos] = sidx;
}

// ---------------- layer-1 gather: batched index+gather phases ---------------
__global__ void __launch_bounds__(256) k_gather1(const float* __restrict__ x) {
    int warp = threadIdx.x >> 5, lane = threadIdx.x & 31;
    int n = blockIdx.x * 8 + warp;
    if (n >= N_NODES) return;
    int deg = g_cursor[n];
    int cnt = deg < CAP ? deg : CAP;
    int off = n * CAP;
    int end = off + cnt;
    int sub = lane >> 3, g = lane & 7;

    float4 acc = make_float4(0.f, 0.f, 0.f, 0.f);
    int e = off + sub;
    while (e < end) {
        int s[8];
#pragma unroll
        for (int i = 0; i < 8; i++) {
            int ee = e + 4 * i;
            s[i] = (ee < end) ? __ldg(&g_csr[ee]) : 0;
        }
#pragma unroll
        for (int i = 0; i < 8; i++) {
            if (e + 4 * i < end) {
                float4 v = __ldg(reinterpret_cast<const float4*>(x + (size_t)s[i] * C1 + g * 4));
                acc.x += v.x; acc.y += v.y; acc.z += v.z; acc.w += v.w;
            }
        }
        e += 32;
    }
#pragma unroll
    for (int d = 16; d >= 8; d >>= 1) {
        acc.x += __shfl_xor_sync(0xffffffff, acc.x, d);
        acc.y += __shfl_xor_sync(0xffffffff, acc.y, d);
        acc.z += __shfl_xor_sync(0xffffffff, acc.z, d);
        acc.w += __shfl_xor_sync(0xffffffff, acc.w, d);
    }
    if (lane < 8) {
        float inv = 1.f / fmaxf((float)deg, 1.f);
        acc.x *= inv; acc.y *= inv; acc.z *= inv; acc.w *= inv;
        *reinterpret_cast<float4*>(g_agg1 + (size_t)n * C1 + g * 4) = acc;
    }
}

// ---------------- layer-1 node update: f32x2, 4 nodes/thread, half-H passes -
__global__ void __launch_bounds__(128, 1) k_node1(const float* __restrict__ x,
                                                  const float* __restrict__ Wl,
                                                  const float* __restrict__ b,
                                                  const float* __restrict__ Wr) {
    __shared__ __align__(16) float sWlT[C1 * H];   // [k][j]
    __shared__ __align__(16) float sWrT[C1 * H];
    __shared__ float sb[H];
    for (int i = threadIdx.x; i < H * C1; i += blockDim.x) {
        int j = i / C1, k = i % C1;
        sWlT[k * H + j] = Wl[i];
        sWrT[k * H + j] = Wr[i];
    }
    for (int i = threadIdx.x; i < H; i += blockDim.x) sb[i] = b[i];
    __syncthreads();

    int n0 = (blockIdx.x * blockDim.x + threadIdx.x) * 4;
    if (n0 >= N_NODES) return;   // N_NODES % 4 == 0

#pragma unroll 1
    for (int jh = 0; jh < 2; jh++) {         // half-H pass: j in [jh*32, jh*32+32)
        int jb = jh * (H / 2);
        unsigned long long acc[4][H / 4];
#pragma unroll
        for (int p = 0; p < H / 4; p++) {
            unsigned long long bb = pack2(sb[jb + 2 * p], sb[jb + 2 * p + 1]);
#pragma unroll
            for (int i = 0; i < 4; i++) acc[i][p] = bb;
        }

#pragma unroll 1
        for (int kc = 0; kc < C1 / 4; kc++) {
            float am[4][4], xm[4][4];
#pragma unroll
            for (int i = 0; i < 4; i++) {
                float4 a = *reinterpret_cast<const float4*>(g_agg1 + (size_t)(n0 + i) * C1 + kc * 4);
                float4 xb = *reinterpret_cast<const float4*>(x + (size_t)(n0 + i) * C1 + kc * 4);
                am[i][0] = a.x; am[i][1] = a.y; am[i][2] = a.z; am[i][3] = a.w;
                xm[i][0] = xb.x; xm[i][1] = xb.y; xm[i][2] = xb.z; xm[i][3] = xb.w;
            }
#pragma unroll
            for (int t = 0; t < 4; t++) {
                int k = kc * 4 + t;
                unsigned long long bm[4], bx[4];
#pragma unroll
                for (int i = 0; i < 4; i++) {
                    bm[i] = bcast2(am[i][t]);
                    bx[i] = bcast2(xm[i][t]);
                }
#pragma unroll
                for (int jq = 0; jq < H / 8; jq++) {   // 8 jq covering half H
                    ulonglong2 wl = *reinterpret_cast<const ulonglong2*>(&sWlT[k * H + jb + jq * 4]);
                    ulonglong2 wr = *reinterpret_cast<const ulonglong2*>(&sWrT[k * H + jb + jq * 4]);
#pragma unroll
                    for (int i = 0; i < 4; i++) {
                        ffma2(acc[i][jq * 2 + 0], bm[i], wl.x);
                        ffma2(acc[i][jq * 2 + 1], bm[i], wl.y);
                        ffma2(acc[i][jq * 2 + 0], bx[i], wr.x);
                        ffma2(acc[i][jq * 2 + 1], bx[i], wr.y);
                    }
                }
            }
        }
#pragma unroll
        for (int i = 0; i < 4; i++) {
#pragma unroll
            for (int jq = 0; jq < H / 8; jq++) {
                float f0, f1, f2, f3;
                unpack2(acc[i][jq * 2 + 0], f0, f1);
                unpack2(acc[i][jq * 2 + 1], f2, f3);
                float4 o;
                o.x = fmaxf(f0, 0.f); o.y = fmaxf(f1, 0.f);
                o.z = fmaxf(f2, 0.f); o.w = fmaxf(f3, 0.f);
                *reinterpret_cast<float4*>(&g_h1[(size_t)(n0 + i) * H + jb + jq * 4]) = o;
            }
        }
    }
}

// ---------------- layer-2 gather: batched index+gather phases ---------------
__global__ void __launch_bounds__(256) k_gather2() {
    int warp = threadIdx.x >> 5, lane = threadIdx.x & 31;
    int n = blockIdx.x * 8 + warp;
    if (n >= N_NODES) return;
    int deg = g_cursor[n];
    int cnt = deg < CAP ? deg : CAP;
    int off = n * CAP;
    int end = off + cnt;
    int sub = lane >> 4, g = lane & 15;

    float4 acc = make_float4(0.f, 0.f, 0.f, 0.f);
    int e = off + sub;
    while (e < end) {
        int s[8];
#pragma unroll
        for (int i = 0; i < 8; i++) {
            int ee = e + 2 * i;
            s[i] = (ee < end) ? __ldg(&g_csr[ee]) : 0;
        }
#pragma unroll
        for (int i = 0; i < 8; i++) {
            if (e + 2 * i < end) {
                float4 v = __ldg(reinterpret_cast<const float4*>(g_h1 + (size_t)s[i] * H + g * 4));
                acc.x += v.x; acc.y += v.y; acc.z += v.z; acc.w += v.w;
            }
        }
        e += 16;
    }
    acc.x += __shfl_xor_sync(0xffffffff, acc.x, 16);
    acc.y += __shfl_xor_sync(0xffffffff, acc.y, 16);
    acc.z += __shfl_xor_sync(0xffffffff, acc.z, 16);
    acc.w += __shfl_xor_sync(0xffffffff, acc.w, 16);
    if (lane < 16) {
        float inv = 1.f / fmaxf((float)deg, 1.f);
        acc.x *= inv; acc.y *= inv; acc.z *= inv; acc.w *= inv;
        *reinterpret_cast<float4*>(g_agg2 + (size_t)n * H + g * 4) = acc;
    }
}

// ---------------- layer-2 node update + pooling: f32x2, 2 nodes/thread ------
__global__ void __launch_bounds__(128, 1) k_node2(const void* __restrict__ batch,
                                                  const float* __restrict__ Wl,
                                                  const float* __restrict__ b,
                                                  const float* __restrict__ Wr) {
    __shared__ __align__(16) float sWlT[H * H];   // [k][j]
    __shared__ __align__(16) float sWrT[H * H];
    __shared__ float sb[H];
    for (int i = threadIdx.x; i < H * H; i += blockDim.x) {
        int j = i / H, k = i % H;
        sWlT[k * H + j] = Wl[i];
        sWrT[k * H + j] = Wr[i];
    }
    for (int i = threadIdx.x; i < H; i += blockDim.x) sb[i] = b[i];
    __syncthreads();

    int n0 = (blockIdx.x * blockDim.x + threadIdx.x) * 2;
    if (n0 >= N_NODES) return;
    int n1 = n0 + 1;

    unsigned long long acc0[H / 2], acc1[H / 2];
#pragma unroll
    for (int p = 0; p < H / 2; p++) {
        unsigned long long bb = pack2(sb[2 * p], sb[2 * p + 1]);
        acc0[p] = bb;
        acc1[p] = bb;
    }

    const float4* ag0 = reinterpret_cast<const float4*>(g_agg2 + (size_t)n0 * H);
    const float4* hr0 = reinterpret_cast<const float4*>(g_h1 + (size_t)n0 * H);
    const float4* ag1 = reinterpret_cast<const float4*>(g_agg2 + (size_t)n1 * H);
    const float4* hr1 = reinterpret_cast<const float4*>(g_h1 + (size_t)n1 * H);

#pragma unroll 1
    for (int kc = 0; kc < H / 4; kc++) {
        float4 a0 = ag0[kc], h0 = hr0[kc];
        float4 a1 = ag1[kc], h1 = hr1[kc];
        float am0[4] = {a0.x, a0.y, a0.z, a0.w};
        float hm0[4] = {h0.x, h0.y, h0.z, h0.w};
        float am1[4] = {a1.x, a1.y, a1.z, a1.w};
        float hm1[4] = {h1.x, h1.y, h1.z, h1.w};
#pragma unroll
        for (int t = 0; t < 4; t++) {
            int k = kc * 4 + t;
            unsigned long long bm0 = bcast2(am0[t]);
            unsigned long long bh0 = bcast2(hm0[t]);
            unsigned long long bm1 = bcast2(am1[t]);
            unsigned long long bh1 = bcast2(hm1[t]);
#pragma unroll
            for (int jq = 0; jq < H / 4; jq++) {
                ulonglong2 wl = *reinterpret_cast<const ulonglong2*>(&sWlT[k * H + jq * 4]);
                ulonglong2 wr = *reinterpret_cast<const ulonglong2*>(&sWrT[k * H + jq * 4]);
                ffma2(acc0[jq * 2 + 0], bm0, wl.x);
                ffma2(acc0[jq * 2 + 1], bm0, wl.y);
                ffma2(acc0[jq * 2 + 0], bh0, wr.x);
                ffma2(acc0[jq * 2 + 1], bh0, wr.y);
                ffma2(acc1[jq * 2 + 0], bm1, wl.x);
                ffma2(acc1[jq * 2 + 1], bm1, wl.y);
                ffma2(acc1[jq * 2 + 0], bh1, wr.x);
                ffma2(acc1[jq * 2 + 1], bh1, wr.y);
            }
        }
    }

    int bg0 = load_idx(batch, n0);
    int bg1 = load_idx(batch, n1);
    float* pr0 = g_pool + (size_t)bg0 * H;
    float* pr1 = g_pool + (size_t)bg1 * H;
#pragma unroll
    for (int jq = 0; jq < H / 4; jq++) {
        float f0, f1, f2, f3;
        unpack2(acc0[jq * 2 + 0], f0, f1);
        unpack2(acc0[jq * 2 + 1], f2, f3);
        float4 o;
        o.x = fmaxf(f0, 0.f); o.y = fmaxf(f1, 0.f);
        o.z = fmaxf(f2, 0.f); o.w = fmaxf(f3, 0.f);
        atomicAdd(reinterpret_cast<float4*>(pr0 + jq * 4), o);
        unpack2(acc1[jq * 2 + 0], f0, f1);
        unpack2(acc1[jq * 2 + 1], f2, f3);
        o.x = fmaxf(f0, 0.f); o.y = fmaxf(f1, 0.f);
        o.z = fmaxf(f2, 0.f); o.w = fmaxf(f3, 0.f);
        atomicAdd(reinterpret_cast<float4*>(pr1 + jq * 4), o);
    }
    atomicAdd(&g_cnt[bg0], 1.0f);
    atomicAdd(&g_cnt[bg1], 1.0f);
}

// ---------------- final linear ----------------------------------------------
__global__ void k_final(const float* __restrict__ Wlin,
                        const float* __restrict__ blin,
                        float* __restrict__ out) {
    int g = blockIdx.x * blockDim.x + threadIdx.x;
    if (g >= N_GRAPHS) return;
    float invc = 1.0f / fmaxf(g_cnt[g], 1.0f);
    float a0 = blin[0], a1 = blin[1];
#pragma unroll
    for (int j = 0; j < H; j++) {
        float p = g_pool[(size_t)g * H + j] * invc;
        a0 += p * Wlin[j];
        a1 += p * Wlin[H + j];
    }
    out[g * 2 + 0] = a0;
    out[g * 2 + 1] = a1;
}

// ---------------------------------------------------------------------------
extern "C" void kernel_launch(void* const* d_in, const int* in_sizes, int n_in,
                              void* d_out, int out_size) {
    const float* x     = (const float*)d_in[0];
    const void*  ei    = d_in[1];
    const void*  batch = d_in[2];
    const float* W1_l  = (const float*)d_in[3];
    const float* b1    = (const float*)d_in[4];
    const float* W1_r  = (const float*)d_in[5];
    const float* W2_l  = (const float*)d_in[6];
    const float* b2    = (const float*)d_in[7];
    const float* W2_r  = (const float*)d_in[8];
    const float* W_lin = (const float*)d_in[9];
    const float* b_lin = (const float*)d_in[10];
    float* out = (float*)d_out;

    int E = in_sizes[1] / 2;
    int eb = (E + 255) / 256;
    int nb8 = (N_NODES + 7) / 8;
    int np4 = (N_NODES / 4 + 127) / 128;   // node-quad blocks (node1)
    int np2 = (N_NODES / 2 + 127) / 128;   // node-pair blocks (node2)

    k_zero<<<256, 256>>>(ei, in_sizes[1]);
    k_scatter<<<eb, 256>>>(ei, E);
    k_gather1<<<nb8, 256>>>(x);
    k_node1<<<np4, 128>>>(x, W1_l, b1, W1_r);
    k_gather2<<<nb8, 256>>>();
    k_node2<<<np2, 128>>>(batch, W2_l, b2, W2_r);
    k_final<<<(N_GRAPHS + 127) / 128, 128>>>(W_lin, b_lin, out);
}